// round 13
// baseline (speedup 1.0000x reference)
#include <cuda_runtime.h>
#include <cuda_bf16.h>
#include <math.h>
#include <cstdint>

#define BB 1024   // batch
#define TT 80     // timesteps
#define EE 512    // embed dim
#define UU 512    // hidden units
#define VV 50000  // vocab

// ---------------- device scratch (allocation-free rule) ----------------
__device__ float g_xk[(size_t)BB * TT * UU];            // [B*T, U] fp32 input projections
__device__ __nv_bfloat16 g_hh[2][(size_t)BB * UU];      // hidden hi, ping-pong
__device__ __nv_bfloat16 g_hl[2][(size_t)BB * UU];      // hidden lo
__device__ __nv_bfloat16 g_Rh[(size_t)UU * UU];         // R^T [n][k] hi
__device__ __nv_bfloat16 g_Rl[(size_t)UU * UU];         // R^T [n][k] lo
__device__ __nv_bfloat16 g_Wh[(size_t)UU * EE];         // W^T [n][k] hi
__device__ __nv_bfloat16 g_Wl[(size_t)UU * EE];         // W^T [n][k] lo
__device__ __nv_bfloat16 g_embh[(size_t)VV * EE];       // emb hi
__device__ __nv_bfloat16 g_embl[(size_t)VV * EE];       // emb lo
__device__ unsigned g_count;                            // grid barrier
__device__ unsigned g_gen;

// ---------------- small helpers ----------------
__device__ __forceinline__ uint32_t smem_u32(const void* p) {
    uint32_t a;
    asm("{ .reg .u64 t; cvta.to.shared.u64 t, %1; cvt.u32.u64 %0, t; }"
        : "=r"(a) : "l"(p));
    return a;
}

__device__ __forceinline__ void cp16(uint32_t s, const void* g) {
    asm volatile("cp.async.cg.shared.global [%0], [%1], 16;"
                 :: "r"(s), "l"(__cvta_generic_to_global(g)) : "memory");
}
__device__ __forceinline__ void cp_commit() {
    asm volatile("cp.async.commit_group;" ::: "memory");
}
__device__ __forceinline__ void cp_wait1() {
    asm volatile("cp.async.wait_group 1;" ::: "memory");
}
__device__ __forceinline__ void cp_wait0() {
    asm volatile("cp.async.wait_group 0;" ::: "memory");
}

__device__ __forceinline__ void ldmx4(uint32_t* r, uint32_t addr) {
    asm volatile("ldmatrix.sync.aligned.m8n8.x4.shared.b16 {%0,%1,%2,%3}, [%4];"
                 : "=r"(r[0]), "=r"(r[1]), "=r"(r[2]), "=r"(r[3]) : "r"(addr));
}

__device__ __forceinline__ void mma16816(float* c, const uint32_t* a, const uint32_t* b) {
    asm volatile(
        "mma.sync.aligned.m16n8k16.row.col.f32.bf16.bf16.f32 "
        "{%0,%1,%2,%3}, {%4,%5,%6,%7}, {%8,%9}, {%0,%1,%2,%3};"
        : "+f"(c[0]), "+f"(c[1]), "+f"(c[2]), "+f"(c[3])
        : "r"(a[0]), "r"(a[1]), "r"(a[2]), "r"(a[3]), "r"(b[0]), "r"(b[1]));
}

// byte swizzle inside a 128B-row tile: rotate 16B unit by row%8
__device__ __forceinline__ uint32_t swz(int row, int kbyte) {
    return (uint32_t)(row * 128 + (kbyte ^ ((row & 7) << 4)));
}

// ---------------- prep kernels ----------------
__global__ void init_sync_kernel() {
    if (threadIdx.x == 0) { g_count = 0u; g_gen = 0u; }
}

// flat fp32 -> bf16 hi/lo split
__global__ void prep_split_flat(const float* __restrict__ src,
                                __nv_bfloat16* __restrict__ dh,
                                __nv_bfloat16* __restrict__ dl, size_t n4) {
    size_t i = (size_t)blockIdx.x * blockDim.x + threadIdx.x;
    if (i >= n4) return;
    float4 v = ((const float4*)src)[i];
    __nv_bfloat16 h0 = __float2bfloat16(v.x), h1 = __float2bfloat16(v.y);
    __nv_bfloat16 h2 = __float2bfloat16(v.z), h3 = __float2bfloat16(v.w);
    __nv_bfloat162 hp0; hp0.x = h0; hp0.y = h1;
    __nv_bfloat162 hp1; hp1.x = h2; hp1.y = h3;
    ((__nv_bfloat162*)dh)[2 * i] = hp0;
    ((__nv_bfloat162*)dh)[2 * i + 1] = hp1;
    __nv_bfloat162 lp0, lp1;
    lp0.x = __float2bfloat16(v.x - __bfloat162float(h0));
    lp0.y = __float2bfloat16(v.y - __bfloat162float(h1));
    lp1.x = __float2bfloat16(v.z - __bfloat162float(h2));
    lp1.y = __float2bfloat16(v.w - __bfloat162float(h3));
    ((__nv_bfloat162*)dl)[2 * i] = lp0;
    ((__nv_bfloat162*)dl)[2 * i + 1] = lp1;
}

// M [k][n] (512x512) -> Mt [n][k] bf16 hi/lo
__global__ void prep_T_split(const float* __restrict__ M,
                             __nv_bfloat16* __restrict__ th,
                             __nv_bfloat16* __restrict__ tl) {
    __shared__ float tile[32][33];
    const int kb = blockIdx.x * 32;
    const int nb = blockIdx.y * 32;
    const int tx = threadIdx.x;
    const int ty = threadIdx.y;
    #pragma unroll
    for (int i = 0; i < 4; i++)
        tile[ty + i * 8][tx] = M[(size_t)(kb + ty + i * 8) * UU + nb + tx];
    __syncthreads();
    #pragma unroll
    for (int i = 0; i < 4; i++) {
        int n = nb + ty + i * 8;
        int k = kb + tx;
        float v = tile[tx][ty + i * 8];
        __nv_bfloat16 hi = __float2bfloat16(v);
        th[(size_t)n * UU + k] = hi;
        tl[(size_t)n * UU + k] = __float2bfloat16(v - __bfloat162float(hi));
    }
}

// ---------------- MMA machinery ----------------
// 32x32 warp tile (2 m16 x 4 n8): used by the scan.
struct Frag2 { float c[2][4][4]; };

__device__ __forceinline__ void compute_stage2(uint32_t a_h, uint32_t a_l,
                                               uint32_t b_h, uint32_t b_l,
                                               int lane, int warp_m, int warp_n,
                                               Frag2& f) {
    #pragma unroll
    for (int kk = 0; kk < 4; kk++) {
        const int kb = kk * 32;
        uint32_t ah[2][4], al[2][4];
        {
            int arow = warp_m + (lane & 15);
            int kadd = kb + ((lane >> 4) << 4);
            #pragma unroll
            for (int mt = 0; mt < 2; mt++) {
                int r = arow + mt * 16;
                uint32_t so = swz(r, kadd);
                ldmx4(ah[mt], a_h + so);
                ldmx4(al[mt], a_l + so);
            }
        }
        uint32_t bhf[2][4], blf[2][4];
        {
            int quad = lane >> 3;
            int nrow = warp_n + (lane & 7) + ((quad >> 1) << 3);
            int kadd = kb + ((quad & 1) << 4);
            #pragma unroll
            for (int p = 0; p < 2; p++) {
                int r = nrow + p * 16;
                uint32_t so = swz(r, kadd);
                ldmx4(bhf[p], b_h + so);
                ldmx4(blf[p], b_l + so);
            }
        }
        #pragma unroll
        for (int mt = 0; mt < 2; mt++)
            #pragma unroll
            for (int nt = 0; nt < 4; nt++) {
                const uint32_t* b2h = &bhf[nt >> 1][(nt & 1) * 2];
                const uint32_t* b2l = &blf[nt >> 1][(nt & 1) * 2];
                mma16816(f.c[mt][nt], ah[mt], b2h);
                mma16816(f.c[mt][nt], ah[mt], b2l);
                mma16816(f.c[mt][nt], al[mt], b2h);
            }
    }
}

// 64x32 warp tile (4 m16 x 4 n8): used by the embed GEMM.
struct Frag4 { float c[4][4][4]; };

__device__ __forceinline__ void compute_stage4(uint32_t a_h, uint32_t a_l,
                                               uint32_t b_h, uint32_t b_l,
                                               int lane, int warp_m, int warp_n,
                                               Frag4& f) {
    #pragma unroll
    for (int kk = 0; kk < 4; kk++) {
        const int kb = kk * 32;
        uint32_t ah[4][4], al[4][4];
        {
            int arow = warp_m + (lane & 15);
            int kadd = kb + ((lane >> 4) << 4);
            #pragma unroll
            for (int mt = 0; mt < 4; mt++) {
                int r = arow + mt * 16;
                uint32_t so = swz(r, kadd);
                ldmx4(ah[mt], a_h + so);
                ldmx4(al[mt], a_l + so);
            }
        }
        uint32_t bhf[2][4], blf[2][4];
        {
            int quad = lane >> 3;
            int nrow = warp_n + (lane & 7) + ((quad >> 1) << 3);
            int kadd = kb + ((quad & 1) << 4);
            #pragma unroll
            for (int p = 0; p < 2; p++) {
                int r = nrow + p * 16;
                uint32_t so = swz(r, kadd);
                ldmx4(bhf[p], b_h + so);
                ldmx4(blf[p], b_l + so);
            }
        }
        #pragma unroll
        for (int mt = 0; mt < 4; mt++)
            #pragma unroll
            for (int nt = 0; nt < 4; nt++) {
                const uint32_t* b2h = &bhf[nt >> 1][(nt & 1) * 2];
                const uint32_t* b2l = &blf[nt >> 1][(nt & 1) * 2];
                mma16816(f.c[mt][nt], ah[mt], b2h);
                mma16816(f.c[mt][nt], ah[mt], b2l);
                mma16816(f.c[mt][nt], al[mt], b2h);
            }
    }
}

// ---------------- embed GEMM: CTA 128M x 128N, 256 threads ----------------
// stage: Ah 16KB | Al 16KB | Bh 16KB | Bl 16KB = 64KB, double buffered.
#define EMB_SMEM (1024 + 131072)

__global__ void __launch_bounds__(256, 1) embed_mma(const int* __restrict__ tokens,
                                                    const float* __restrict__ bias) {
    extern __shared__ char smem[];
    __shared__ int s_tok[128];
    const uint32_t sb = smem_u32(smem);
    const uint32_t bufb = (sb + 1023) & ~1023u;
    const int tid = threadIdx.x;
    const int lane = tid & 31;
    const int wid = tid >> 5;
    const int warp_m = (wid & 1) * 64;      // 2 warps in m
    const int warp_n = (wid >> 1) * 32;     // 4 warps in n
    const int m0 = blockIdx.x * 128;
    const int n0 = blockIdx.y * 128;

    if (tid < 128) s_tok[tid] = tokens[m0 + tid];
    __syncthreads();

    auto fill = [&](int s) {
        const uint32_t bb = bufb + (uint32_t)(s & 1) * 65536;
        const int k0 = s * 64;
        #pragma unroll
        for (int it = 0; it < 4; it++) {
            int u = tid + it * 256;
            int row = u >> 3, c8 = u & 7;
            uint32_t so = swz(row, c8 * 16);
            size_t as = (size_t)s_tok[row] * EE + k0 + c8 * 8;
            cp16(bb + so, g_embh + as);
            cp16(bb + 16384 + so, g_embl + as);
            size_t bs = (size_t)(n0 + row) * EE + k0 + c8 * 8;
            cp16(bb + 32768 + so, g_Wh + bs);
            cp16(bb + 49152 + so, g_Wl + bs);
        }
    };

    Frag4 f;
    #pragma unroll
    for (int mt = 0; mt < 4; mt++)
        #pragma unroll
        for (int nt = 0; nt < 4; nt++)
            #pragma unroll
            for (int q = 0; q < 4; q++) f.c[mt][nt][q] = 0.0f;

    fill(0);
    cp_commit();
    for (int s = 0; s < 8; s++) {
        if (s < 7) { fill(s + 1); cp_commit(); cp_wait1(); }
        else cp_wait0();
        __syncthreads();
        uint32_t bb = bufb + (uint32_t)(s & 1) * 65536;
        compute_stage4(bb, bb + 16384, bb + 32768, bb + 49152,
                       lane, warp_m, warp_n, f);
        __syncthreads();
    }

    #pragma unroll
    for (int mt = 0; mt < 4; mt++)
        #pragma unroll
        for (int nt = 0; nt < 4; nt++) {
            int row = m0 + warp_m + mt * 16 + (lane >> 2);
            int col = n0 + warp_n + nt * 8 + (lane & 3) * 2;
            float2 bv = *(const float2*)&bias[col];
            #pragma unroll
            for (int h2 = 0; h2 < 2; h2++) {
                int m = row + h2 * 8;
                float2 o;
                o.x = f.c[mt][nt][h2 * 2 + 0] + bv.x;
                o.y = f.c[mt][nt][h2 * 2 + 1] + bv.y;
                *(float2*)&g_xk[(size_t)m * UU + col] = o;
            }
        }
}

// ---------------- persistent fused scan (R10-passing version) ----------------
// 128 CTAs: m0 = (bid&15)*64, n0 = (bid>>4)*64. R tile resident in smem.
// smem: [R: 8 chunks x 8KB hi (64KB), then lo (64KB)] [h stages: 2 x 16KB] [xk: 16KB]
#define SCAN_RL   65536
#define SCAN_HB   131072
#define SCAN_XK   163840
#define SCAN_SMEM (1024 + 180224)
#define NCTA      128

__device__ __forceinline__ void grid_bar() {
    __syncthreads();
    if (threadIdx.x == 0) {
        unsigned gen = atomicAdd(&g_gen, 0u);
        __threadfence();
        if (atomicAdd(&g_count, 1u) == NCTA - 1u) {
            g_count = 0u;
            __threadfence();
            atomicExch(&g_gen, gen + 1u);
        } else {
            while (atomicAdd(&g_gen, 0u) == gen) { __nanosleep(64); }
            __threadfence();
        }
    }
    __syncthreads();
}

__global__ void __launch_bounds__(128, 1) rnn_scan_persistent(
    const float* __restrict__ fc_w,
    const float* __restrict__ fc_b,
    float* __restrict__ out)
{
    extern __shared__ char smem[];
    const uint32_t sb = smem_u32(smem);
    const uint32_t rb = (sb + 1023) & ~1023u;
    const int tid = threadIdx.x;
    const int lane = tid & 31;
    const int wid = tid >> 5;
    const int warp_m = (wid & 1) * 32;
    const int warp_n = (wid >> 1) * 32;
    const int m0 = (blockIdx.x & 15) * 64;
    const int n0 = (blockIdx.x >> 4) * 64;

    // ---- load R tile (once): 64 n-rows x 512 k, hi+lo, 8 chunks of 8KB ----
    for (int i = tid; i < 4096; i += 128) {
        int chunk = i >> 9;
        int r = (i & 511) >> 3;
        int c8 = i & 7;
        uint32_t so = (uint32_t)(chunk * 8192) + swz(r, c8 * 16);
        size_t src = (size_t)(n0 + r) * UU + chunk * 64 + c8 * 8;
        cp16(rb + so, g_Rh + src);
        cp16(rb + SCAN_RL + so, g_Rl + src);
    }
    cp_commit();

    // ---- t = 0: h1 = tanh(xk[:,0,:]) (no GEMM) ----
    for (int i = tid; i < 2048; i += 128) {
        int r = i >> 5, c2 = i & 31;
        int m = m0 + r, n = n0 + c2 * 2;
        float2 xv = *(const float2*)&g_xk[((size_t)m * TT + 0) * UU + n];
        float v0 = tanhf(xv.x);
        float v1 = tanhf(xv.y);
        __nv_bfloat16 p0 = __float2bfloat16(v0);
        __nv_bfloat16 p1 = __float2bfloat16(v1);
        __nv_bfloat162 hp; hp.x = p0; hp.y = p1;
        *(__nv_bfloat162*)&g_hh[1][(size_t)m * UU + n] = hp;
        __nv_bfloat162 lp;
        lp.x = __float2bfloat16(v0 - __bfloat162float(p0));
        lp.y = __float2bfloat16(v1 - __bfloat162float(p1));
        *(__nv_bfloat162*)&g_hl[1][(size_t)m * UU + n] = lp;
    }
    cp_wait0();   // R resident
    grid_bar();

    // ---- steps t = 1..79: h_{t+1} = tanh(xk[:,t,:] + h_t @ R) ----
    for (int t = 1; t < TT; t++) {
        const __nv_bfloat16* __restrict__ sh = g_hh[t & 1];
        const __nv_bfloat16* __restrict__ sl = g_hl[t & 1];
        __nv_bfloat16* __restrict__ dh = g_hh[(t + 1) & 1];
        __nv_bfloat16* __restrict__ dl = g_hl[(t + 1) & 1];

        auto fillh = [&](int s) {
            const uint32_t hb = rb + SCAN_HB + (uint32_t)(s & 1) * 16384;
            const int k0 = s * 64;
            #pragma unroll
            for (int it = 0; it < 4; it++) {
                int u = tid + it * 128;
                int row = u >> 3, c8 = u & 7;
                uint32_t so = swz(row, c8 * 16);
                size_t src = (size_t)(m0 + row) * UU + k0 + c8 * 8;
                cp16(hb + so, sh + src);
                cp16(hb + 8192 + so, sl + src);
            }
        };

        Frag2 f;
        #pragma unroll
        for (int mt = 0; mt < 2; mt++)
            #pragma unroll
            for (int nt = 0; nt < 4; nt++)
                #pragma unroll
                for (int q = 0; q < 4; q++) f.c[mt][nt][q] = 0.0f;

        fillh(0);
        // xk tile prefetch into smem (independent of h), same cp group as stage 0
        for (int i = tid; i < 1024; i += 128) {
            int r = i >> 4, c4 = i & 15;
            cp16(rb + SCAN_XK + (uint32_t)(r * 256 + c4 * 16),
                 &g_xk[((size_t)(m0 + r) * TT + t) * UU + n0 + c4 * 4]);
        }
        cp_commit();

        for (int s = 0; s < 8; s++) {
            if (s < 7) { fillh(s + 1); cp_commit(); cp_wait1(); }
            else cp_wait0();
            __syncthreads();
            const uint32_t hb = rb + SCAN_HB + (uint32_t)(s & 1) * 16384;
            compute_stage2(hb, hb + 8192,
                           rb + (uint32_t)(s * 8192),
                           rb + SCAN_RL + (uint32_t)(s * 8192),
                           lane, warp_m, warp_n, f);
            __syncthreads();
        }

        #pragma unroll
        for (int mt = 0; mt < 2; mt++)
            #pragma unroll
            for (int nt = 0; nt < 4; nt++) {
                int rl = warp_m + mt * 16 + (lane >> 2);
                int cl = warp_n + nt * 8 + (lane & 3) * 2;
                #pragma unroll
                for (int h2 = 0; h2 < 2; h2++) {
                    int rr = rl + h2 * 8;
                    float2 xv;
                    asm volatile("ld.shared.v2.f32 {%0,%1}, [%2];"
                                 : "=f"(xv.x), "=f"(xv.y)
                                 : "r"(rb + SCAN_XK + (uint32_t)(rr * 256 + cl * 4)));
                    float v0 = tanhf(f.c[mt][nt][h2 * 2 + 0] + xv.x);
                    float v1 = tanhf(f.c[mt][nt][h2 * 2 + 1] + xv.y);
                    int m = m0 + rr, n = n0 + cl;
                    __nv_bfloat16 p0 = __float2bfloat16(v0);
                    __nv_bfloat16 p1 = __float2bfloat16(v1);
                    __nv_bfloat162 hp; hp.x = p0; hp.y = p1;
                    *(__nv_bfloat162*)&dh[(size_t)m * UU + n] = hp;
                    __nv_bfloat162 lp;
                    lp.x = __float2bfloat16(v0 - __bfloat162float(p0));
                    lp.y = __float2bfloat16(v1 - __bfloat162float(p1));
                    *(__nv_bfloat162*)&dl[(size_t)m * UU + n] = lp;
                }
            }
        grid_bar();
    }

    // ---- head on n0==0 CTAs: out[b] = sigmoid(h80 . fc_w + fc_b) ----
    if (n0 == 0) {
        const __nv_bfloat16* __restrict__ hh = g_hh[0];  // 80 & 1 == 0
        const __nv_bfloat16* __restrict__ hl = g_hl[0];
        const float fb = fc_b[0];
        for (int rr = 0; rr < 16; rr++) {
            int b = m0 + wid * 16 + rr;
            float s = 0.0f;
            #pragma unroll
            for (int it = 0; it < 16; it++) {
                int u = lane + it * 32;
                float hv = __bfloat162float(hh[(size_t)b * UU + u])
                         + __bfloat162float(hl[(size_t)b * UU + u]);
                s = fmaf(hv, fc_w[u], s);
            }
            #pragma unroll
            for (int o = 16; o > 0; o >>= 1) s += __shfl_xor_sync(0xffffffffu, s, o);
            if (lane == 0) out[b] = 1.0f / (1.0f + expf(-(s + fb)));
        }
    }
}

// ---------------- launch ----------------
extern "C" void kernel_launch(void* const* d_in, const int* in_sizes, int n_in,
                              void* d_out, int out_size)
{
    const int*   tokens = (const int*)  d_in[0];
    const float* emb    = (const float*)d_in[1];
    const float* W      = (const float*)d_in[2];
    const float* R      = (const float*)d_in[3];
    const float* bias   = (const float*)d_in[4];
    const float* fc_w   = (const float*)d_in[5];
    const float* fc_b   = (const float*)d_in[6];
    float* out = (float*)d_out;

    cudaFuncSetAttribute(embed_mma,
                         cudaFuncAttributeMaxDynamicSharedMemorySize, EMB_SMEM);
    cudaFuncSetAttribute(rnn_scan_persistent,
                         cudaFuncAttributeMaxDynamicSharedMemorySize, SCAN_SMEM);

    init_sync_kernel<<<1, 32>>>();

    __nv_bfloat16 *embh, *embl, *wh, *wl, *rh, *rl;
    cudaGetSymbolAddress((void**)&embh, g_embh);
    cudaGetSymbolAddress((void**)&embl, g_embl);
    cudaGetSymbolAddress((void**)&wh, g_Wh);
    cudaGetSymbolAddress((void**)&wl, g_Wl);
    cudaGetSymbolAddress((void**)&rh, g_Rh);
    cudaGetSymbolAddress((void**)&rl, g_Rl);

    const size_t emb_n4 = (size_t)VV * EE / 4;
    prep_split_flat<<<(unsigned)((emb_n4 + 255) / 256), 256>>>(emb, embh, embl, emb_n4);
    prep_T_split<<<dim3(UU / 32, UU / 32), dim3(32, 8)>>>(W, wh, wl);
    prep_T_split<<<dim3(UU / 32, UU / 32), dim3(32, 8)>>>(R, rh, rl);

    dim3 g1(BB * TT / 128, UU / 128);   // 640 x 4
    embed_mma<<<g1, 256, EMB_SMEM>>>(tokens, bias);

    rnn_scan_persistent<<<NCTA, 128, SCAN_SMEM>>>(fc_w, fc_b, out);
}

// round 16
// speedup vs baseline: 1.0962x; 1.0962x over previous
#include <cuda_runtime.h>
#include <cuda_bf16.h>
#include <math.h>
#include <cstdint>

#define BB 1024   // batch
#define TT 80     // timesteps
#define EE 512    // embed dim
#define UU 512    // hidden units
#define VV 50000  // vocab
#define VP 50048  // vocab padded to 128

// ---------------- device scratch (allocation-free rule) ----------------
__device__ float g_P[(size_t)VP * UU];                  // P = emb @ W + bias  [V, U] fp32
__device__ __nv_bfloat16 g_hh[2][(size_t)BB * UU];      // hidden hi, ping-pong
__device__ __nv_bfloat16 g_hl[2][(size_t)BB * UU];      // hidden lo
__device__ __nv_bfloat16 g_Rh[(size_t)UU * UU];         // R^T [n][k] hi
__device__ __nv_bfloat16 g_Rl[(size_t)UU * UU];         // R^T [n][k] lo
__device__ __nv_bfloat16 g_Wh[(size_t)UU * EE];         // W^T [n][k] hi
__device__ __nv_bfloat16 g_Wl[(size_t)UU * EE];         // W^T [n][k] lo
__device__ __nv_bfloat16 g_embh[(size_t)VV * EE];       // emb hi
__device__ __nv_bfloat16 g_embl[(size_t)VV * EE];       // emb lo
__device__ unsigned g_count;                            // grid barrier
__device__ unsigned g_gen;

// ---------------- small helpers ----------------
__device__ __forceinline__ uint32_t smem_u32(const void* p) {
    uint32_t a;
    asm("{ .reg .u64 t; cvta.to.shared.u64 t, %1; cvt.u32.u64 %0, t; }"
        : "=r"(a) : "l"(p));
    return a;
}

__device__ __forceinline__ void cp16(uint32_t s, const void* g) {
    asm volatile("cp.async.cg.shared.global [%0], [%1], 16;"
                 :: "r"(s), "l"(__cvta_generic_to_global(g)) : "memory");
}
__device__ __forceinline__ void cp_commit() {
    asm volatile("cp.async.commit_group;" ::: "memory");
}
__device__ __forceinline__ void cp_wait1() {
    asm volatile("cp.async.wait_group 1;" ::: "memory");
}
__device__ __forceinline__ void cp_wait0() {
    asm volatile("cp.async.wait_group 0;" ::: "memory");
}

__device__ __forceinline__ void ldmx4(uint32_t* r, uint32_t addr) {
    asm volatile("ldmatrix.sync.aligned.m8n8.x4.shared.b16 {%0,%1,%2,%3}, [%4];"
                 : "=r"(r[0]), "=r"(r[1]), "=r"(r[2]), "=r"(r[3]) : "r"(addr));
}

__device__ __forceinline__ void mma16816(float* c, const uint32_t* a, const uint32_t* b) {
    asm volatile(
        "mma.sync.aligned.m16n8k16.row.col.f32.bf16.bf16.f32 "
        "{%0,%1,%2,%3}, {%4,%5,%6,%7}, {%8,%9}, {%0,%1,%2,%3};"
        : "+f"(c[0]), "+f"(c[1]), "+f"(c[2]), "+f"(c[3])
        : "r"(a[0]), "r"(a[1]), "r"(a[2]), "r"(a[3]), "r"(b[0]), "r"(b[1]));
}

// byte swizzle inside a 128B-row tile: rotate 16B unit by row%8
__device__ __forceinline__ uint32_t swz(int row, int kbyte) {
    return (uint32_t)(row * 128 + (kbyte ^ ((row & 7) << 4)));
}

// ---------------- prep kernels ----------------
__global__ void init_sync_kernel() {
    if (threadIdx.x == 0) { g_count = 0u; g_gen = 0u; }
}

// flat fp32 -> bf16 hi/lo split
__global__ void prep_split_flat(const float* __restrict__ src,
                                __nv_bfloat16* __restrict__ dh,
                                __nv_bfloat16* __restrict__ dl, size_t n4) {
    size_t i = (size_t)blockIdx.x * blockDim.x + threadIdx.x;
    if (i >= n4) return;
    float4 v = ((const float4*)src)[i];
    __nv_bfloat16 h0 = __float2bfloat16(v.x), h1 = __float2bfloat16(v.y);
    __nv_bfloat16 h2 = __float2bfloat16(v.z), h3 = __float2bfloat16(v.w);
    __nv_bfloat162 hp0; hp0.x = h0; hp0.y = h1;
    __nv_bfloat162 hp1; hp1.x = h2; hp1.y = h3;
    ((__nv_bfloat162*)dh)[2 * i] = hp0;
    ((__nv_bfloat162*)dh)[2 * i + 1] = hp1;
    __nv_bfloat162 lp0, lp1;
    lp0.x = __float2bfloat16(v.x - __bfloat162float(h0));
    lp0.y = __float2bfloat16(v.y - __bfloat162float(h1));
    lp1.x = __float2bfloat16(v.z - __bfloat162float(h2));
    lp1.y = __float2bfloat16(v.w - __bfloat162float(h3));
    ((__nv_bfloat162*)dl)[2 * i] = lp0;
    ((__nv_bfloat162*)dl)[2 * i + 1] = lp1;
}

// M [k][n] (512x512) -> Mt [n][k] bf16 hi/lo
__global__ void prep_T_split(const float* __restrict__ M,
                             __nv_bfloat16* __restrict__ th,
                             __nv_bfloat16* __restrict__ tl) {
    __shared__ float tile[32][33];
    const int kb = blockIdx.x * 32;
    const int nb = blockIdx.y * 32;
    const int tx = threadIdx.x;
    const int ty = threadIdx.y;
    #pragma unroll
    for (int i = 0; i < 4; i++)
        tile[ty + i * 8][tx] = M[(size_t)(kb + ty + i * 8) * UU + nb + tx];
    __syncthreads();
    #pragma unroll
    for (int i = 0; i < 4; i++) {
        int n = nb + ty + i * 8;
        int k = kb + tx;
        float v = tile[tx][ty + i * 8];
        __nv_bfloat16 hi = __float2bfloat16(v);
        th[(size_t)n * UU + k] = hi;
        tl[(size_t)n * UU + k] = __float2bfloat16(v - __bfloat162float(hi));
    }
}

// ---------------- MMA machinery ----------------
// 32x32 warp tile (2 m16 x 4 n8): used by the scan.
struct Frag2 { float c[2][4][4]; };

__device__ __forceinline__ void compute_stage2(uint32_t a_h, uint32_t a_l,
                                               uint32_t b_h, uint32_t b_l,
                                               int lane, int warp_m, int warp_n,
                                               Frag2& f) {
    #pragma unroll
    for (int kk = 0; kk < 4; kk++) {
        const int kb = kk * 32;
        uint32_t ah[2][4], al[2][4];
        {
            int arow = warp_m + (lane & 15);
            int kadd = kb + ((lane >> 4) << 4);
            #pragma unroll
            for (int mt = 0; mt < 2; mt++) {
                int r = arow + mt * 16;
                uint32_t so = swz(r, kadd);
                ldmx4(ah[mt], a_h + so);
                ldmx4(al[mt], a_l + so);
            }
        }
        uint32_t bhf[2][4], blf[2][4];
        {
            int quad = lane >> 3;
            int nrow = warp_n + (lane & 7) + ((quad >> 1) << 3);
            int kadd = kb + ((quad & 1) << 4);
            #pragma unroll
            for (int p = 0; p < 2; p++) {
                int r = nrow + p * 16;
                uint32_t so = swz(r, kadd);
                ldmx4(bhf[p], b_h + so);
                ldmx4(blf[p], b_l + so);
            }
        }
        #pragma unroll
        for (int mt = 0; mt < 2; mt++)
            #pragma unroll
            for (int nt = 0; nt < 4; nt++) {
                const uint32_t* b2h = &bhf[nt >> 1][(nt & 1) * 2];
                const uint32_t* b2l = &blf[nt >> 1][(nt & 1) * 2];
                mma16816(f.c[mt][nt], ah[mt], b2h);
                mma16816(f.c[mt][nt], ah[mt], b2l);
                mma16816(f.c[mt][nt], al[mt], b2h);
            }
    }
}

// 64x32 warp tile (4 m16 x 4 n8): used by the vocab GEMM.
struct Frag4 { float c[4][4][4]; };

__device__ __forceinline__ void compute_stage4(uint32_t a_h, uint32_t a_l,
                                               uint32_t b_h, uint32_t b_l,
                                               int lane, int warp_m, int warp_n,
                                               Frag4& f) {
    #pragma unroll
    for (int kk = 0; kk < 4; kk++) {
        const int kb = kk * 32;
        uint32_t ah[4][4], al[4][4];
        {
            int arow = warp_m + (lane & 15);
            int kadd = kb + ((lane >> 4) << 4);
            #pragma unroll
            for (int mt = 0; mt < 4; mt++) {
                int r = arow + mt * 16;
                uint32_t so = swz(r, kadd);
                ldmx4(ah[mt], a_h + so);
                ldmx4(al[mt], a_l + so);
            }
        }
        uint32_t bhf[2][4], blf[2][4];
        {
            int quad = lane >> 3;
            int nrow = warp_n + (lane & 7) + ((quad >> 1) << 3);
            int kadd = kb + ((quad & 1) << 4);
            #pragma unroll
            for (int p = 0; p < 2; p++) {
                int r = nrow + p * 16;
                uint32_t so = swz(r, kadd);
                ldmx4(bhf[p], b_h + so);
                ldmx4(blf[p], b_l + so);
            }
        }
        #pragma unroll
        for (int mt = 0; mt < 4; mt++)
            #pragma unroll
            for (int nt = 0; nt < 4; nt++) {
                const uint32_t* b2h = &bhf[nt >> 1][(nt & 1) * 2];
                const uint32_t* b2l = &blf[nt >> 1][(nt & 1) * 2];
                mma16816(f.c[mt][nt], ah[mt], b2h);
                mma16816(f.c[mt][nt], ah[mt], b2l);
                mma16816(f.c[mt][nt], al[mt], b2h);
            }
    }
}

// ---------------- vocab GEMM: P = emb @ W + bias, CTA 128M x 128N ----------------
// stage: Ah 16KB | Al 16KB | Bh 16KB | Bl 16KB = 64KB, double buffered.
#define EMB_SMEM (1024 + 131072)

__global__ void __launch_bounds__(256, 1) vocab_mma(const float* __restrict__ bias) {
    extern __shared__ char smem[];
    const uint32_t sb = smem_u32(smem);
    const uint32_t bufb = (sb + 1023) & ~1023u;
    const int tid = threadIdx.x;
    const int lane = tid & 31;
    const int wid = tid >> 5;
    const int warp_m = (wid & 1) * 64;      // 2 warps in m
    const int warp_n = (wid >> 1) * 32;     // 4 warps in n
    const int m0 = blockIdx.x * 128;
    const int n0 = blockIdx.y * 128;

    auto fill = [&](int s) {
        const uint32_t bb = bufb + (uint32_t)(s & 1) * 65536;
        const int k0 = s * 64;
        #pragma unroll
        for (int it = 0; it < 4; it++) {
            int u = tid + it * 256;
            int row = u >> 3, c8 = u & 7;
            uint32_t so = swz(row, c8 * 16);
            int ar = m0 + row; if (ar >= VV) ar = VV - 1;   // clamp tail rows
            size_t as = (size_t)ar * EE + k0 + c8 * 8;
            cp16(bb + so, g_embh + as);
            cp16(bb + 16384 + so, g_embl + as);
            size_t bs = (size_t)(n0 + row) * EE + k0 + c8 * 8;
            cp16(bb + 32768 + so, g_Wh + bs);
            cp16(bb + 49152 + so, g_Wl + bs);
        }
    };

    Frag4 f;
    #pragma unroll
    for (int mt = 0; mt < 4; mt++)
        #pragma unroll
        for (int nt = 0; nt < 4; nt++)
            #pragma unroll
            for (int q = 0; q < 4; q++) f.c[mt][nt][q] = 0.0f;

    fill(0);
    cp_commit();
    for (int s = 0; s < 8; s++) {
        if (s < 7) { fill(s + 1); cp_commit(); cp_wait1(); }
        else cp_wait0();
        __syncthreads();
        uint32_t bb = bufb + (uint32_t)(s & 1) * 65536;
        compute_stage4(bb, bb + 16384, bb + 32768, bb + 49152,
                       lane, warp_m, warp_n, f);
        __syncthreads();
    }

    #pragma unroll
    for (int mt = 0; mt < 4; mt++)
        #pragma unroll
        for (int nt = 0; nt < 4; nt++) {
            int row = m0 + warp_m + mt * 16 + (lane >> 2);
            int col = n0 + warp_n + nt * 8 + (lane & 3) * 2;
            float2 bv = *(const float2*)&bias[col];
            #pragma unroll
            for (int h2 = 0; h2 < 2; h2++) {
                int m = row + h2 * 8;
                if (m < VV) {
                    float2 o;
                    o.x = f.c[mt][nt][h2 * 2 + 0] + bv.x;
                    o.y = f.c[mt][nt][h2 * 2 + 1] + bv.y;
                    *(float2*)&g_P[(size_t)m * UU + col] = o;
                }
            }
        }
}

// ---------------- persistent fused scan (R10 structure; xk <- P[token]) ----------------
// 128 CTAs: m0 = (bid&15)*64, n0 = (bid>>4)*64. R tile resident in smem.
// smem: [R: 8 chunks x 8KB hi (64KB), then lo (64KB)] [h stages: 2 x 16KB] [xk: 16KB]
#define SCAN_RL   65536
#define SCAN_HB   131072
#define SCAN_XK   163840
#define SCAN_SMEM (1024 + 180224)
#define NCTA      128

__device__ __forceinline__ void grid_bar() {
    __syncthreads();
    if (threadIdx.x == 0) {
        unsigned gen = atomicAdd(&g_gen, 0u);
        __threadfence();
        if (atomicAdd(&g_count, 1u) == NCTA - 1u) {
            g_count = 0u;
            __threadfence();
            atomicExch(&g_gen, gen + 1u);
        } else {
            while (atomicAdd(&g_gen, 0u) == gen) { __nanosleep(64); }
            __threadfence();
        }
    }
    __syncthreads();
}

__global__ void __launch_bounds__(128, 1) rnn_scan_persistent(
    const int* __restrict__ tokens,
    const float* __restrict__ fc_w,
    const float* __restrict__ fc_b,
    float* __restrict__ out)
{
    extern __shared__ char smem[];
    const uint32_t sb = smem_u32(smem);
    const uint32_t rb = (sb + 1023) & ~1023u;
    const int tid = threadIdx.x;
    const int lane = tid & 31;
    const int wid = tid >> 5;
    const int warp_m = (wid & 1) * 32;
    const int warp_n = (wid >> 1) * 32;
    const int m0 = (blockIdx.x & 15) * 64;
    const int n0 = (blockIdx.x >> 4) * 64;

    // ---- load R tile (once): 64 n-rows x 512 k, hi+lo, 8 chunks of 8KB ----
    for (int i = tid; i < 4096; i += 128) {
        int chunk = i >> 9;
        int r = (i & 511) >> 3;
        int c8 = i & 7;
        uint32_t so = (uint32_t)(chunk * 8192) + swz(r, c8 * 16);
        size_t src = (size_t)(n0 + r) * UU + chunk * 64 + c8 * 8;
        cp16(rb + so, g_Rh + src);
        cp16(rb + SCAN_RL + so, g_Rl + src);
    }
    cp_commit();

    // ---- t = 0: h1 = tanh(P[tok[m][0]]) (no GEMM) ----
    for (int i = tid; i < 2048; i += 128) {
        int r = i >> 5, c2 = i & 31;
        int m = m0 + r, n = n0 + c2 * 2;
        int tok = __ldg(&tokens[m * TT + 0]);
        float2 xv = *(const float2*)&g_P[(size_t)tok * UU + n];
        float v0 = tanhf(xv.x);
        float v1 = tanhf(xv.y);
        __nv_bfloat16 p0 = __float2bfloat16(v0);
        __nv_bfloat16 p1 = __float2bfloat16(v1);
        __nv_bfloat162 hp; hp.x = p0; hp.y = p1;
        *(__nv_bfloat162*)&g_hh[1][(size_t)m * UU + n] = hp;
        __nv_bfloat162 lp;
        lp.x = __float2bfloat16(v0 - __bfloat162float(p0));
        lp.y = __float2bfloat16(v1 - __bfloat162float(p1));
        *(__nv_bfloat162*)&g_hl[1][(size_t)m * UU + n] = lp;
    }
    cp_wait0();   // R resident
    grid_bar();

    // ---- steps t = 1..79: h_{t+1} = tanh(P[tok[m][t]] + h_t @ R) ----
    for (int t = 1; t < TT; t++) {
        const __nv_bfloat16* __restrict__ sh = g_hh[t & 1];
        const __nv_bfloat16* __restrict__ sl = g_hl[t & 1];
        __nv_bfloat16* __restrict__ dh = g_hh[(t + 1) & 1];
        __nv_bfloat16* __restrict__ dl = g_hl[(t + 1) & 1];

        auto fillh = [&](int s) {
            const uint32_t hb = rb + SCAN_HB + (uint32_t)(s & 1) * 16384;
            const int k0 = s * 64;
            #pragma unroll
            for (int it = 0; it < 4; it++) {
                int u = tid + it * 128;
                int row = u >> 3, c8 = u & 7;
                uint32_t so = swz(row, c8 * 16);
                size_t src = (size_t)(m0 + row) * UU + k0 + c8 * 8;
                cp16(hb + so, sh + src);
                cp16(hb + 8192 + so, sl + src);
            }
        };

        Frag2 f;
        #pragma unroll
        for (int mt = 0; mt < 2; mt++)
            #pragma unroll
            for (int nt = 0; nt < 4; nt++)
                #pragma unroll
                for (int q = 0; q < 4; q++) f.c[mt][nt][q] = 0.0f;

        fillh(0);
        // P-row tile prefetch into smem (gather by token), same cp group as stage 0
        #pragma unroll
        for (int it = 0; it < 8; it++) {
            int i = tid + it * 128;
            int r = i >> 4, c4 = i & 15;
            int tok = __ldg(&tokens[(m0 + r) * TT + t]);
            cp16(rb + SCAN_XK + (uint32_t)(r * 256 + c4 * 16),
                 &g_P[(size_t)tok * UU + n0 + c4 * 4]);
        }
        cp_commit();

        for (int s = 0; s < 8; s++) {
            if (s < 7) { fillh(s + 1); cp_commit(); cp_wait1(); }
            else cp_wait0();
            __syncthreads();
            const uint32_t hb = rb + SCAN_HB + (uint32_t)(s & 1) * 16384;
            compute_stage2(hb, hb + 8192,
                           rb + (uint32_t)(s * 8192),
                           rb + SCAN_RL + (uint32_t)(s * 8192),
                           lane, warp_m, warp_n, f);
            __syncthreads();
        }

        #pragma unroll
        for (int mt = 0; mt < 2; mt++)
            #pragma unroll
            for (int nt = 0; nt < 4; nt++) {
                int rl = warp_m + mt * 16 + (lane >> 2);
                int cl = warp_n + nt * 8 + (lane & 3) * 2;
                #pragma unroll
                for (int h2 = 0; h2 < 2; h2++) {
                    int rr = rl + h2 * 8;
                    float2 xv;
                    asm volatile("ld.shared.v2.f32 {%0,%1}, [%2];"
                                 : "=f"(xv.x), "=f"(xv.y)
                                 : "r"(rb + SCAN_XK + (uint32_t)(rr * 256 + cl * 4)));
                    float v0 = tanhf(f.c[mt][nt][h2 * 2 + 0] + xv.x);
                    float v1 = tanhf(f.c[mt][nt][h2 * 2 + 1] + xv.y);
                    int m = m0 + rr, n = n0 + cl;
                    __nv_bfloat16 p0 = __float2bfloat16(v0);
                    __nv_bfloat16 p1 = __float2bfloat16(v1);
                    __nv_bfloat162 hp; hp.x = p0; hp.y = p1;
                    *(__nv_bfloat162*)&dh[(size_t)m * UU + n] = hp;
                    __nv_bfloat162 lp;
                    lp.x = __float2bfloat16(v0 - __bfloat162float(p0));
                    lp.y = __float2bfloat16(v1 - __bfloat162float(p1));
                    *(__nv_bfloat162*)&dl[(size_t)m * UU + n] = lp;
                }
            }
        grid_bar();
    }

    // ---- head on n0==0 CTAs: out[b] = sigmoid(h80 . fc_w + fc_b) ----
    if (n0 == 0) {
        const __nv_bfloat16* __restrict__ hh = g_hh[0];  // 80 & 1 == 0
        const __nv_bfloat16* __restrict__ hl = g_hl[0];
        const float fb = fc_b[0];
        for (int rr = 0; rr < 16; rr++) {
            int b = m0 + wid * 16 + rr;
            float s = 0.0f;
            #pragma unroll
            for (int it = 0; it < 16; it++) {
                int u = lane + it * 32;
                float hv = __bfloat162float(hh[(size_t)b * UU + u])
                         + __bfloat162float(hl[(size_t)b * UU + u]);
                s = fmaf(hv, fc_w[u], s);
            }
            #pragma unroll
            for (int o = 16; o > 0; o >>= 1) s += __shfl_xor_sync(0xffffffffu, s, o);
            if (lane == 0) out[b] = 1.0f / (1.0f + expf(-(s + fb)));
        }
    }
}

// ---------------- launch ----------------
extern "C" void kernel_launch(void* const* d_in, const int* in_sizes, int n_in,
                              void* d_out, int out_size)
{
    const int*   tokens = (const int*)  d_in[0];
    const float* emb    = (const float*)d_in[1];
    const float* W      = (const float*)d_in[2];
    const float* R      = (const float*)d_in[3];
    const float* bias   = (const float*)d_in[4];
    const float* fc_w   = (const float*)d_in[5];
    const float* fc_b   = (const float*)d_in[6];
    float* out = (float*)d_out;

    cudaFuncSetAttribute(vocab_mma,
                         cudaFuncAttributeMaxDynamicSharedMemorySize, EMB_SMEM);
    cudaFuncSetAttribute(rnn_scan_persistent,
                         cudaFuncAttributeMaxDynamicSharedMemorySize, SCAN_SMEM);

    init_sync_kernel<<<1, 32>>>();

    __nv_bfloat16 *embh, *embl, *wh, *wl, *rh, *rl;
    cudaGetSymbolAddress((void**)&embh, g_embh);
    cudaGetSymbolAddress((void**)&embl, g_embl);
    cudaGetSymbolAddress((void**)&wh, g_Wh);
    cudaGetSymbolAddress((void**)&wl, g_Wl);
    cudaGetSymbolAddress((void**)&rh, g_Rh);
    cudaGetSymbolAddress((void**)&rl, g_Rl);

    const size_t emb_n4 = (size_t)VV * EE / 4;
    prep_split_flat<<<(unsigned)((emb_n4 + 255) / 256), 256>>>(emb, embh, embl, emb_n4);
    prep_T_split<<<dim3(UU / 32, UU / 32), dim3(32, 8)>>>(W, wh, wl);
    prep_T_split<<<dim3(UU / 32, UU / 32), dim3(32, 8)>>>(R, rh, rl);

    dim3 g1(VP / 128, UU / 128);   // 391 x 4
    vocab_mma<<<g1, 256, EMB_SMEM>>>(bias);

    rnn_scan_persistent<<<NCTA, 128, SCAN_SMEM>>>(tokens, fc_w, fc_b, out);
}